// round 8
// baseline (speedup 1.0000x reference)
#include <cuda_runtime.h>
#include <cuda_fp16.h>
#include <cstdint>
#include <math.h>

#define NBATCH 4
#define TSEQ   2048
#define DMODEL 1024
#define NHEADS 16
#define HDIM   64
#define MROWS  (NBATCH * TSEQ)   // 8192
#define KDIM   DMODEL            // 1024
#define D3     (3 * DMODEL)

// ---------------- scratch (static device globals; no runtime alloc) --------
__device__ __align__(1024) __half g_xh[(size_t)MROWS * DMODEL];        // 16 MB
__device__ __align__(1024) __half g_qkvh[(size_t)MROWS * D3];          // 50 MB
__device__ __align__(1024) __half g_yh[(size_t)MROWS * DMODEL];        // 16 MB
__device__ __align__(1024) __half g_wqkvh[(size_t)KDIM * D3];          // 6 MB
__device__ __align__(1024) __half g_woh[(size_t)KDIM * DMODEL];        // 2 MB

// ---------------- helpers ---------------------------------------------------
#define CP_ASYNC16(dst, src) \
    asm volatile("cp.async.cg.shared.global [%0], [%1], 16;" \
                 :: "r"(dst), "l"(src) : "memory")
#define CP_COMMIT() asm volatile("cp.async.commit_group;" ::: "memory")
#define CP_WAIT2()  asm volatile("cp.async.wait_group 2;" ::: "memory")
#define CP_WAIT0()  asm volatile("cp.async.wait_group 0;" ::: "memory")

__device__ __forceinline__ uint32_t smem_u32(const void* p) {
    uint32_t a;
    asm("{ .reg .u64 t; cvta.to.shared.u64 t, %1; cvt.u32.u64 %0, t; }"
        : "=r"(a) : "l"(p));
    return a;
}

#define MMA_F16(d, a, b) \
    asm volatile("mma.sync.aligned.m16n8k16.row.col.f32.f16.f16.f32 " \
        "{%0,%1,%2,%3}, {%4,%5,%6,%7}, {%8,%9}, {%0,%1,%2,%3};" \
        : "+f"((d)[0]), "+f"((d)[1]), "+f"((d)[2]), "+f"((d)[3]) \
        : "r"((a)[0]), "r"((a)[1]), "r"((a)[2]), "r"((a)[3]), \
          "r"((b)[0]), "r"((b)[1]))

#define LDSM_X4(r0, r1, r2, r3, addr) \
    asm volatile("ldmatrix.sync.aligned.m8n8.x4.shared.b16 {%0,%1,%2,%3}, [%4];" \
        : "=r"(r0), "=r"(r1), "=r"(r2), "=r"(r3) : "r"(addr))
#define LDSM_X4_T(r0, r1, r2, r3, addr) \
    asm volatile("ldmatrix.sync.aligned.m8n8.x4.trans.shared.b16 {%0,%1,%2,%3}, [%4];" \
        : "=r"(r0), "=r"(r1), "=r"(r2), "=r"(r3) : "r"(addr))

__device__ __forceinline__ void store_pair(float* p, float a, float b) {
    *(float2*)p = make_float2(a, b);
}
__device__ __forceinline__ void store_pair(__half* p, float a, float b) {
    *(__half2*)p = __floats2half2_rn(a, b);
}

// ---------------- prep: fp32 -> fp16 streaming convert ---------------------
__global__ void f2h_kernel(const float* __restrict__ in,
                           __half* __restrict__ out, int n4) {
    for (int i = blockIdx.x * blockDim.x + threadIdx.x; i < n4;
         i += gridDim.x * blockDim.x) {
        float4 v = *(const float4*)(in + (size_t)i * 4);
        __half2 h0 = __floats2half2_rn(v.x, v.y);
        __half2 h1 = __floats2half2_rn(v.z, v.w);
        *(uint2*)(out + (size_t)i * 4) =
            make_uint2(*(uint32_t*)&h0, *(uint32_t*)&h1);
    }
}

// ---------------- fp16 mma GEMM ---------------------------------------------
// C[M,N] = A[M,K] @ W[K,N] + bias.  W used directly (no pre-transpose):
// B tile staged [BK=32][N=128] and B-fragments pulled via ldmatrix.x4.trans.
// CTA 128x128, 4-stage cp.async, 256 thr (8 warps 4x2, 32x64 each).
#define HBK 32
#define HPH 40                               // A tile pitch (halves)
#define BNP 136                              // B tile pitch (halves)
#define ATILE_H (128 * HPH)                  // 5120 halves
#define BTILE_H (HBK * BNP)                  // 4352 halves
#define STAGE_H (ATILE_H + BTILE_H)          // 9472 halves
#define HSMEM_BYTES (4 * STAGE_H * 2)        // 75776 B
#define HCHUNKS (KDIM / HBK)                 // 32

template <typename OutT>
__global__ __launch_bounds__(256, 2) void gemm_h_kernel(
    const __half* __restrict__ A, const __half* __restrict__ W,
    const float* __restrict__ bias, OutT* __restrict__ C, int N)
{
    extern __shared__ __half hsm[];
    const int tid = threadIdx.x;
    const int wid = tid >> 5;
    const int lane = tid & 31;
    const int gid = lane >> 2;
    const int tig = lane & 3;

    const size_t row0 = (size_t)blockIdx.y * 128;
    const size_t col0 = (size_t)blockIdx.x * 128;
    const int wm0 = (wid & 3) * 32;
    const int wn0 = (wid >> 2) * 64;

    const __half* Ab = A + row0 * KDIM;

    float acc[2][8][4];
#pragma unroll
    for (int mt = 0; mt < 2; mt++)
#pragma unroll
        for (int nt = 0; nt < 8; nt++)
#pragma unroll
            for (int j = 0; j < 4; j++) acc[mt][nt][j] = 0.f;

    const uint32_t sbase = smem_u32(hsm);

    // ldmatrix lane patterns
    const int aRow = lane & 15, aColSel = (lane >> 4) * 8;          // A (normal)
    const int tRow = (lane & 7) + (((lane >> 3) & 1) << 3);         // B (trans)
    const int tColSel = (lane >> 4) * 8;

    auto load_stage = [&](int s, int chunk) {
        const int kof = chunk * HBK;
        uint32_t aS = sbase + (uint32_t)(s * STAGE_H) * 2u;
        uint32_t bS = aS + (uint32_t)ATILE_H * 2u;
        // A: 128 rows x 32 halves (512 x 16B)
#pragma unroll
        for (int i = 0; i < 2; i++) {
            int idx = tid + i * 256;
            int r = idx >> 2, ch = idx & 3;
            CP_ASYNC16(aS + (uint32_t)(r * HPH + ch * 8) * 2u,
                       Ab + (size_t)r * KDIM + kof + ch * 8);
        }
        // B: 32 rows x 128 halves (512 x 16B), straight from W[K,N]
#pragma unroll
        for (int i = 0; i < 2; i++) {
            int idx = tid + i * 256;
            int r = idx >> 4, ch = idx & 15;
            CP_ASYNC16(bS + (uint32_t)(r * BNP + ch * 8) * 2u,
                       W + (size_t)(kof + r) * N + col0 + ch * 8);
        }
    };

    load_stage(0, 0); CP_COMMIT();
    load_stage(1, 1); CP_COMMIT();
    load_stage(2, 2); CP_COMMIT();

    for (int c = 0; c < HCHUNKS; c++) {
        CP_WAIT2();
        __syncthreads();          // single barrier: orders prev compute vs. overwrite
        if (c + 3 < HCHUNKS) load_stage((c + 3) & 3, c + 3);
        CP_COMMIT();

        const uint32_t aS = sbase + (uint32_t)((c & 3) * STAGE_H) * 2u;
        const uint32_t bS = aS + (uint32_t)ATILE_H * 2u;
#pragma unroll
        for (int kk = 0; kk < 2; kk++) {
            const int kb = kk * 16;
            uint32_t a[2][4];
#pragma unroll
            for (int mt = 0; mt < 2; mt++) {
                uint32_t ad = aS + (uint32_t)((wm0 + mt * 16 + aRow) * HPH + kb + aColSel) * 2u;
                LDSM_X4(a[mt][0], a[mt][1], a[mt][2], a[mt][3], ad);
            }
            uint32_t b[8][2];
#pragma unroll
            for (int np = 0; np < 4; np++) {
                uint32_t bd = bS + (uint32_t)((kb + tRow) * BNP + wn0 + np * 16 + tColSel) * 2u;
                LDSM_X4_T(b[2 * np][0], b[2 * np][1], b[2 * np + 1][0], b[2 * np + 1][1], bd);
            }
#pragma unroll
            for (int mt = 0; mt < 2; mt++)
#pragma unroll
                for (int nt = 0; nt < 8; nt++)
                    MMA_F16(acc[mt][nt], a[mt], b[nt]);
        }
    }

#pragma unroll
    for (int mt = 0; mt < 2; mt++) {
        size_t r = row0 + wm0 + mt * 16 + gid;
#pragma unroll
        for (int nt = 0; nt < 8; nt++) {
            size_t col = col0 + wn0 + nt * 8 + tig * 2;
            float2 bb = *(const float2*)(bias + col);
            store_pair(C + r * N + col, acc[mt][nt][0] + bb.x, acc[mt][nt][1] + bb.y);
            store_pair(C + (r + 8) * N + col, acc[mt][nt][2] + bb.x, acc[mt][nt][3] + bb.y);
        }
    }
}

// ---------------- fp16 flash attention (cp.async 2-stage K/V) --------------
// Per CTA one (b, h, 128-q tile); 8 warps x 16 q-rows; 64-key tiles.
// K/V double-buffered via cp.async; ONE __syncthreads per tile.
// Diagonal-tile trimming: MMA/store loops bounded by kkmax per warp.
#define APH 72
#define KVT_H (64 * APH)                       // halves per K or V tile
#define ATT_SMEM_BYTES ((4 * KVT_H + 128 * APH) * 2)   // 55296 B

__global__ __launch_bounds__(256, 2) void attn_h_kernel(
    const __half* __restrict__ qkv, __half* __restrict__ y)
{
    extern __shared__ __half dsm[];
    // stage s: K at s*2*KVT_H, V at +KVT_H ; Ps after both stages
    __half* Ps = dsm + 4 * KVT_H;

    const int qb  = gridDim.x - 1 - blockIdx.x;
    const int bh  = blockIdx.y;
    const int b   = bh >> 4;
    const int h   = bh & 15;
    const int tid = threadIdx.x;
    const int wid = tid >> 5;
    const int lane = tid & 31;
    const int gid = lane >> 2;
    const int tig = lane & 3;
    const int wrow = wid * 16;
    const int q0 = qb * 128;

    const __half* base = qkv + (size_t)b * TSEQ * D3;
    const uint32_t smS = smem_u32(dsm);
    const uint32_t psS = smem_u32(Ps);

    const int aRow = lane & 15, aColSel = (lane >> 4) * 8;          // Q/P frags
    const int bRow = (lane & 7) + ((lane >> 4) << 3);               // K frags
    const int bColSel = ((lane >> 3) & 1) * 8;
    const int vRow = (lane & 7) + (((lane >> 3) & 1) << 3);         // V trans frags
    const int vColSel = (lane >> 4) * 8;

    const int ntiles = (qb + 1) * 2;

    auto load_kv = [&](int t, int s) {
        const int k0 = t * 64;
        uint32_t kS = smS + (uint32_t)(s * 2 * KVT_H) * 2u;
        uint32_t vS = kS + (uint32_t)KVT_H * 2u;
        const __half* kb_ = base + (size_t)k0 * D3 + DMODEL + h * HDIM;
#pragma unroll
        for (int i = 0; i < 2; i++) {
            int idx = tid + i * 256;
            int r = idx >> 3, ch = idx & 7;
            uint32_t off = (uint32_t)(r * APH + ch * 8) * 2u;
            const __half* src = kb_ + (size_t)r * D3 + ch * 8;
            CP_ASYNC16(kS + off, src);
            CP_ASYNC16(vS + off, src + DMODEL);
        }
    };

    // prologue: kick off tile 0 load, then stage Q while it flies
    load_kv(0, 0); CP_COMMIT();

    {
        const __half2 s = __float2half2_rn(0.125f);
#pragma unroll
        for (int i = 0; i < 4; i++) {
            int idx = tid + i * 256;
            int r = idx >> 3, c8 = (idx & 7) << 3;
            uint4 v = *(const uint4*)(base + (size_t)(q0 + r) * D3 + h * HDIM + c8);
            __half2* h2 = reinterpret_cast<__half2*>(&v);
            h2[0] = __hmul2(h2[0], s); h2[1] = __hmul2(h2[1], s);
            h2[2] = __hmul2(h2[2], s); h2[3] = __hmul2(h2[3], s);
            *(uint4*)&Ps[r * APH + c8] = v;
        }
    }
    __syncthreads();

    uint32_t qf[4][4];
#pragma unroll
    for (int kk = 0; kk < 4; kk++) {
        uint32_t ad = psS + (uint32_t)((wrow + aRow) * APH + kk * 16 + aColSel) * 2u;
        LDSM_X4(qf[kk][0], qf[kk][1], qf[kk][2], qf[kk][3], ad);
    }

    const int r0g = q0 + wrow + gid;
    const int r1g = r0g + 8;
    const int rlast = q0 + wrow + 15;          // warp's last q row

    float m0 = -1e30f, m1 = -1e30f, l0 = 0.f, l1 = 0.f;
    float oacc[8][4];
#pragma unroll
    for (int nt = 0; nt < 8; nt++)
#pragma unroll
        for (int j = 0; j < 4; j++) oacc[nt][j] = 0.f;

    for (int t = 0; t < ntiles; t++) {
        const int k0 = t * 64;
        CP_WAIT0();
        __syncthreads();                        // data visible + prev reads done
        if (t + 1 < ntiles) load_kv(t + 1, (t + 1) & 1);
        CP_COMMIT();

        if (k0 > rlast) continue;               // warp fully masked

        const uint32_t kS = smS + (uint32_t)((t & 1) * 2 * KVT_H) * 2u;
        const uint32_t vS = kS + (uint32_t)KVT_H * 2u;

        const int rel = (rlast - k0) >> 3;          // >= 0
        const int ntmax = rel < 7 ? rel + 1 : 8;    // nt count for S MMA
        const int kkmax = (ntmax + 1) >> 1;         // 16-key groups to process
        const int ntproc = 2 * kkmax;               // nt count for mask/store

        // ---- S = Q @ K^T ----
        float sacc[8][4];
#pragma unroll
        for (int nt = 0; nt < 8; nt++)
#pragma unroll
            for (int j = 0; j < 4; j++) sacc[nt][j] = 0.f;
#pragma unroll
        for (int kk = 0; kk < 4; kk++) {
            const int kb = kk * 16;
            uint32_t bf[8][2];
#pragma unroll
            for (int np = 0; np < 4; np++) {
                if (np >= kkmax) break;
                uint32_t bd = kS + (uint32_t)((np * 16 + bRow) * APH + kb + bColSel) * 2u;
                LDSM_X4(bf[2 * np][0], bf[2 * np][1], bf[2 * np + 1][0], bf[2 * np + 1][1], bd);
            }
#pragma unroll
            for (int nt = 0; nt < 8; nt++) {
                if (nt >= ntmax) break;
                MMA_F16(sacc[nt], qf[kk], bf[nt]);
            }
        }

        // ---- causal mask + quad row max ----
        float tmax0 = -1e30f, tmax1 = -1e30f;
#pragma unroll
        for (int nt = 0; nt < 8; nt++) {
            if (nt >= ntproc) break;
            int col = k0 + nt * 8 + 2 * tig;
            if (col     > r0g) sacc[nt][0] = -1e30f;
            if (col + 1 > r0g) sacc[nt][1] = -1e30f;
            if (col     > r1g) sacc[nt][2] = -1e30f;
            if (col + 1 > r1g) sacc[nt][3] = -1e30f;
            tmax0 = fmaxf(tmax0, fmaxf(sacc[nt][0], sacc[nt][1]));
            tmax1 = fmaxf(tmax1, fmaxf(sacc[nt][2], sacc[nt][3]));
        }
#pragma unroll
        for (int d = 1; d <= 2; d <<= 1) {
            tmax0 = fmaxf(tmax0, __shfl_xor_sync(0xffffffffu, tmax0, d));
            tmax1 = fmaxf(tmax1, __shfl_xor_sync(0xffffffffu, tmax1, d));
        }

        float mn0 = fmaxf(m0, tmax0), mn1 = fmaxf(m1, tmax1);
        float c0 = __expf(m0 - mn0), c1 = __expf(m1 - mn1);
        l0 *= c0; l1 *= c1; m0 = mn0; m1 = mn1;
#pragma unroll
        for (int nt = 0; nt < 8; nt++) {
            oacc[nt][0] *= c0; oacc[nt][1] *= c0;
            oacc[nt][2] *= c1; oacc[nt][3] *= c1;
        }

        // ---- P = exp(S - m); partial l; store P (warp-private rows) ----
        __syncwarp();
#pragma unroll
        for (int nt = 0; nt < 8; nt++) {
            if (nt >= ntproc) break;
            float p0 = __expf(sacc[nt][0] - m0);
            float p1 = __expf(sacc[nt][1] - m0);
            float p2 = __expf(sacc[nt][2] - m1);
            float p3 = __expf(sacc[nt][3] - m1);
            l0 += p0 + p1; l1 += p2 + p3;
            int col = nt * 8 + 2 * tig;
            *(__half2*)&Ps[(wrow + gid    ) * APH + col] = __floats2half2_rn(p0, p1);
            *(__half2*)&Ps[(wrow + gid + 8) * APH + col] = __floats2half2_rn(p2, p3);
        }
        __syncwarp();

        // ---- O += P @ V (only unmasked 16-key groups) ----
#pragma unroll
        for (int kk = 0; kk < 4; kk++) {
            if (kk >= kkmax) break;
            const int kb = kk * 16;
            uint32_t a[4];
            {
                uint32_t ad = psS + (uint32_t)((wrow + aRow) * APH + kb + aColSel) * 2u;
                LDSM_X4(a[0], a[1], a[2], a[3], ad);
            }
            uint32_t bv[8][2];
#pragma unroll
            for (int np = 0; np < 4; np++) {
                uint32_t vd = vS + (uint32_t)((kb + vRow) * APH + np * 16 + vColSel) * 2u;
                LDSM_X4_T(bv[2 * np][0], bv[2 * np][1], bv[2 * np + 1][0], bv[2 * np + 1][1], vd);
            }
#pragma unroll
            for (int nt = 0; nt < 8; nt++)
                MMA_F16(oacc[nt], a, bv[nt]);
        }
    }

    // ---- quad-reduce partial row sums, normalize, store half y ----
#pragma unroll
    for (int d = 1; d <= 2; d <<= 1) {
        l0 += __shfl_xor_sync(0xffffffffu, l0, d);
        l1 += __shfl_xor_sync(0xffffffffu, l1, d);
    }
    float inv0 = 1.f / l0, inv1 = 1.f / l1;
    __half* y0 = y + (size_t)(b * TSEQ + r0g) * DMODEL + h * HDIM;
    __half* y1 = y + (size_t)(b * TSEQ + r1g) * DMODEL + h * HDIM;
#pragma unroll
    for (int nt = 0; nt < 8; nt++) {
        int col = nt * 8 + 2 * tig;
        *(__half2*)(y0 + col) = __floats2half2_rn(oacc[nt][0] * inv0, oacc[nt][1] * inv0);
        *(__half2*)(y1 + col) = __floats2half2_rn(oacc[nt][2] * inv1, oacc[nt][3] * inv1);
    }
}

// ---------------------------------------------------------------------------
extern "C" void kernel_launch(void* const* d_in, const int* in_sizes, int n_in,
                              void* d_out, int out_size)
{
    (void)in_sizes; (void)n_in; (void)out_size;
    const float* x     = (const float*)d_in[0];
    const float* qkv_w = (const float*)d_in[1];
    const float* qkv_b = (const float*)d_in[2];
    const float* o_w   = (const float*)d_in[3];
    const float* o_b   = (const float*)d_in[4];
    float* out = (float*)d_out;

    __half *xh, *qkvh, *yh, *wqkvh, *woh;
    cudaGetSymbolAddress((void**)&xh, g_xh);
    cudaGetSymbolAddress((void**)&qkvh, g_qkvh);
    cudaGetSymbolAddress((void**)&yh, g_yh);
    cudaGetSymbolAddress((void**)&wqkvh, g_wqkvh);
    cudaGetSymbolAddress((void**)&woh, g_woh);

    cudaFuncSetAttribute(gemm_h_kernel<__half>,
                         cudaFuncAttributeMaxDynamicSharedMemorySize, HSMEM_BYTES);
    cudaFuncSetAttribute(gemm_h_kernel<float>,
                         cudaFuncAttributeMaxDynamicSharedMemorySize, HSMEM_BYTES);
    cudaFuncSetAttribute(attn_h_kernel,
                         cudaFuncAttributeMaxDynamicSharedMemorySize, ATT_SMEM_BYTES);

    // prep: pure streaming fp32 -> fp16 (no transposes)
    f2h_kernel<<<1024, 256>>>(x, xh, MROWS * DMODEL / 4);
    f2h_kernel<<<512, 256>>>(qkv_w, wqkvh, KDIM * D3 / 4);
    f2h_kernel<<<256, 256>>>(o_w, woh, KDIM * DMODEL / 4);

    // 1) QKV projection
    gemm_h_kernel<__half><<<dim3(D3 / 128, MROWS / 128), 256, HSMEM_BYTES>>>(
        xh, wqkvh, qkv_b, qkvh, D3);

    // 2) causal flash attention
    attn_h_kernel<<<dim3(TSEQ / 128, NBATCH * NHEADS), 256, ATT_SMEM_BYTES>>>(
        qkvh, yh);

    // 3) output projection
    gemm_h_kernel<float><<<dim3(DMODEL / 128, MROWS / 128), 256, HSMEM_BYTES>>>(
        yh, woh, o_b, out, DMODEL);
}

// round 9
// speedup vs baseline: 1.0756x; 1.0756x over previous
#include <cuda_runtime.h>
#include <cuda_fp16.h>
#include <cstdint>
#include <math.h>

#define NBATCH 4
#define TSEQ   2048
#define DMODEL 1024
#define NHEADS 16
#define HDIM   64
#define MROWS  (NBATCH * TSEQ)   // 8192
#define KDIM   DMODEL            // 1024
#define D3     (3 * DMODEL)

// ---------------- scratch (static device globals; no runtime alloc) --------
__device__ __align__(1024) __half g_xh[(size_t)MROWS * DMODEL];        // 16 MB
__device__ __align__(1024) __half g_qkvh[(size_t)MROWS * D3];          // 50 MB
__device__ __align__(1024) __half g_yh[(size_t)MROWS * DMODEL];        // 16 MB
__device__ __align__(1024) __half g_wqkvh[(size_t)KDIM * D3];          // 6 MB
__device__ __align__(1024) __half g_woh[(size_t)KDIM * DMODEL];        // 2 MB

// ---------------- helpers ---------------------------------------------------
#define CP_ASYNC16(dst, src) \
    asm volatile("cp.async.cg.shared.global [%0], [%1], 16;" \
                 :: "r"(dst), "l"(src) : "memory")
#define CP_COMMIT() asm volatile("cp.async.commit_group;" ::: "memory")
#define CP_WAIT1()  asm volatile("cp.async.wait_group 1;" ::: "memory")

__device__ __forceinline__ uint32_t smem_u32(const void* p) {
    uint32_t a;
    asm("{ .reg .u64 t; cvta.to.shared.u64 t, %1; cvt.u32.u64 %0, t; }"
        : "=r"(a) : "l"(p));
    return a;
}

#define MMA_F16(d, a, b) \
    asm volatile("mma.sync.aligned.m16n8k16.row.col.f32.f16.f16.f32 " \
        "{%0,%1,%2,%3}, {%4,%5,%6,%7}, {%8,%9}, {%0,%1,%2,%3};" \
        : "+f"((d)[0]), "+f"((d)[1]), "+f"((d)[2]), "+f"((d)[3]) \
        : "r"((a)[0]), "r"((a)[1]), "r"((a)[2]), "r"((a)[3]), \
          "r"((b)[0]), "r"((b)[1]))

#define LDSM_X4(r0, r1, r2, r3, addr) \
    asm volatile("ldmatrix.sync.aligned.m8n8.x4.shared.b16 {%0,%1,%2,%3}, [%4];" \
        : "=r"(r0), "=r"(r1), "=r"(r2), "=r"(r3) : "r"(addr))
#define LDSM_X4_T(r0, r1, r2, r3, addr) \
    asm volatile("ldmatrix.sync.aligned.m8n8.x4.trans.shared.b16 {%0,%1,%2,%3}, [%4];" \
        : "=r"(r0), "=r"(r1), "=r"(r2), "=r"(r3) : "r"(addr))

__device__ __forceinline__ void store_pair(float* p, float a, float b) {
    *(float2*)p = make_float2(a, b);
}
__device__ __forceinline__ void store_pair(__half* p, float a, float b) {
    *(__half2*)p = __floats2half2_rn(a, b);
}

// ---------------- prep: fp32 -> fp16 streaming convert ---------------------
__global__ void f2h_kernel(const float* __restrict__ in,
                           __half* __restrict__ out, int n4) {
    for (int i = blockIdx.x * blockDim.x + threadIdx.x; i < n4;
         i += gridDim.x * blockDim.x) {
        float4 v = *(const float4*)(in + (size_t)i * 4);
        __half2 h0 = __floats2half2_rn(v.x, v.y);
        __half2 h1 = __floats2half2_rn(v.z, v.w);
        *(uint2*)(out + (size_t)i * 4) =
            make_uint2(*(uint32_t*)&h0, *(uint32_t*)&h1);
    }
}

// ---------------- fp16 mma GEMM (BK=64, direct W, 1 barrier/chunk) ---------
// C[M,N] = A[M,K] @ W[K,N] + bias.  CTA 128x128, BK=64 halves, 3-stage
// cp.async, 256 thr (8 warps 4x2, 32x64 each).  B-frags via ldmatrix.trans.
// Pitches: A=72 halves, B=136 halves -> ldmatrix row-groups on banks
// 4r mod 32 (disjoint).
#define GBK 64
#define GAP 72                               // A tile pitch (halves)
#define GBP 136                              // B tile pitch (halves)
#define ATILE_H (128 * GAP)                  // 9216 halves
#define BTILE_H (GBK * GBP)                  // 8704 halves
#define STAGE_H (ATILE_H + BTILE_H)          // 17920 halves
#define HSMEM_BYTES (3 * STAGE_H * 2)        // 107520 B
#define GCHUNKS (KDIM / GBK)                 // 16

template <typename OutT>
__global__ __launch_bounds__(256, 2) void gemm_h_kernel(
    const __half* __restrict__ A, const __half* __restrict__ W,
    const float* __restrict__ bias, OutT* __restrict__ C, int N)
{
    extern __shared__ __half hsm[];
    const int tid = threadIdx.x;
    const int wid = tid >> 5;
    const int lane = tid & 31;
    const int gid = lane >> 2;
    const int tig = lane & 3;

    const size_t row0 = (size_t)blockIdx.y * 128;
    const size_t col0 = (size_t)blockIdx.x * 128;
    const int wm0 = (wid & 3) * 32;
    const int wn0 = (wid >> 2) * 64;

    const __half* Ab = A + row0 * KDIM;

    float acc[2][8][4];
#pragma unroll
    for (int mt = 0; mt < 2; mt++)
#pragma unroll
        for (int nt = 0; nt < 8; nt++)
#pragma unroll
            for (int j = 0; j < 4; j++) acc[mt][nt][j] = 0.f;

    const uint32_t sbase = smem_u32(hsm);

    const int aRow = lane & 15, aColSel = (lane >> 4) * 8;          // A (normal)
    const int tRow = (lane & 7) + (((lane >> 3) & 1) << 3);         // B (trans)
    const int tColSel = (lane >> 4) * 8;

    auto load_stage = [&](int s, int chunk) {
        const int kof = chunk * GBK;
        uint32_t aS = sbase + (uint32_t)(s * STAGE_H) * 2u;
        uint32_t bS = aS + (uint32_t)ATILE_H * 2u;
        // A: 128 rows x 64 halves = 1024 x 16B
#pragma unroll
        for (int i = 0; i < 4; i++) {
            int idx = tid + i * 256;
            int r = idx >> 3, ch = idx & 7;
            CP_ASYNC16(aS + (uint32_t)(r * GAP + ch * 8) * 2u,
                       Ab + (size_t)r * KDIM + kof + ch * 8);
        }
        // B: 64 rows x 128 halves = 1024 x 16B, straight from W[K,N]
#pragma unroll
        for (int i = 0; i < 4; i++) {
            int idx = tid + i * 256;
            int r = idx >> 4, ch = idx & 15;
            CP_ASYNC16(bS + (uint32_t)(r * GBP + ch * 8) * 2u,
                       W + (size_t)(kof + r) * N + col0 + ch * 8);
        }
    };

    load_stage(0, 0); CP_COMMIT();
    load_stage(1, 1); CP_COMMIT();

    for (int c = 0; c < GCHUNKS; c++) {
        CP_WAIT1();
        __syncthreads();          // stage c ready; prev compute done before overwrite
        if (c + 2 < GCHUNKS) load_stage((c + 2) % 3, c + 2);
        CP_COMMIT();

        const uint32_t aS = sbase + (uint32_t)((c % 3) * STAGE_H) * 2u;
        const uint32_t bS = aS + (uint32_t)ATILE_H * 2u;
#pragma unroll
        for (int kk = 0; kk < 4; kk++) {
            const int kb = kk * 16;
            uint32_t a[2][4];
#pragma unroll
            for (int mt = 0; mt < 2; mt++) {
                uint32_t ad = aS + (uint32_t)((wm0 + mt * 16 + aRow) * GAP + kb + aColSel) * 2u;
                LDSM_X4(a[mt][0], a[mt][1], a[mt][2], a[mt][3], ad);
            }
            uint32_t b[8][2];
#pragma unroll
            for (int np = 0; np < 4; np++) {
                uint32_t bd = bS + (uint32_t)((kb + tRow) * GBP + wn0 + np * 16 + tColSel) * 2u;
                LDSM_X4_T(b[2 * np][0], b[2 * np][1], b[2 * np + 1][0], b[2 * np + 1][1], bd);
            }
#pragma unroll
            for (int mt = 0; mt < 2; mt++)
#pragma unroll
                for (int nt = 0; nt < 8; nt++)
                    MMA_F16(acc[mt][nt], a[mt], b[nt]);
        }
    }

#pragma unroll
    for (int mt = 0; mt < 2; mt++) {
        size_t r = row0 + wm0 + mt * 16 + gid;
#pragma unroll
        for (int nt = 0; nt < 8; nt++) {
            size_t col = col0 + wn0 + nt * 8 + tig * 2;
            float2 bb = *(const float2*)(bias + col);
            store_pair(C + r * N + col, acc[mt][nt][0] + bb.x, acc[mt][nt][1] + bb.y);
            store_pair(C + (r + 8) * N + col, acc[mt][nt][2] + bb.x, acc[mt][nt][3] + bb.y);
        }
    }
}

// ---------------- fp16 flash attention (R7 version, reverted) --------------
// Per CTA one (b, h, 128-q tile); 8 warps x 16 q-rows; 64-key tiles.
// Ks[key][hd], Vs[key][hd] (V B-frags via ldmatrix.trans), Ps staging.
#define APH 72

__global__ __launch_bounds__(256, 2) void attn_h_kernel(
    const __half* __restrict__ qkv, __half* __restrict__ y)
{
    __shared__ __half Ks[64 * APH];
    __shared__ __half Vs[64 * APH];
    __shared__ __half Ps[128 * APH];

    const int qb  = gridDim.x - 1 - blockIdx.x;
    const int bh  = blockIdx.y;
    const int b   = bh >> 4;
    const int h   = bh & 15;
    const int tid = threadIdx.x;
    const int wid = tid >> 5;
    const int lane = tid & 31;
    const int gid = lane >> 2;
    const int tig = lane & 3;
    const int wrow = wid * 16;
    const int q0 = qb * 128;

    const __half* base = qkv + (size_t)b * TSEQ * D3;
    const uint32_t ksS = smem_u32(Ks);
    const uint32_t vsS = smem_u32(Vs);
    const uint32_t psS = smem_u32(Ps);

    const int aRow = lane & 15, aColSel = (lane >> 4) * 8;
    const int bRow = (lane & 7) + ((lane >> 4) << 3);
    const int bColSel = ((lane >> 3) & 1) * 8;
    const int vRow = (lane & 7) + (((lane >> 3) & 1) << 3);
    const int vColSel = (lane >> 4) * 8;

    {
        const __half2 s = __float2half2_rn(0.125f);
#pragma unroll
        for (int i = 0; i < 4; i++) {
            int idx = tid + i * 256;
            int r = idx >> 3, c8 = (idx & 7) << 3;
            uint4 v = *(const uint4*)(base + (size_t)(q0 + r) * D3 + h * HDIM + c8);
            __half2* h2 = reinterpret_cast<__half2*>(&v);
            h2[0] = __hmul2(h2[0], s); h2[1] = __hmul2(h2[1], s);
            h2[2] = __hmul2(h2[2], s); h2[3] = __hmul2(h2[3], s);
            *(uint4*)&Ps[r * APH + c8] = v;
        }
    }
    __syncthreads();

    uint32_t qf[4][4];
#pragma unroll
    for (int kk = 0; kk < 4; kk++) {
        uint32_t ad = psS + (uint32_t)((wrow + aRow) * APH + kk * 16 + aColSel) * 2u;
        LDSM_X4(qf[kk][0], qf[kk][1], qf[kk][2], qf[kk][3], ad);
    }
    __syncthreads();

    const int r0g = q0 + wrow + gid;
    const int r1g = r0g + 8;

    float m0 = -1e30f, m1 = -1e30f, l0 = 0.f, l1 = 0.f;
    float oacc[8][4];
#pragma unroll
    for (int nt = 0; nt < 8; nt++)
#pragma unroll
        for (int j = 0; j < 4; j++) oacc[nt][j] = 0.f;

    const int ntiles = (qb + 1) * 2;
    for (int t = 0; t < ntiles; t++) {
        const int k0 = t * 64;
        __syncthreads();
#pragma unroll
        for (int i = 0; i < 2; i++) {
            int idx = tid + i * 256;
            int r = idx >> 3, c8 = (idx & 7) << 3;
            const __half* kr = base + (size_t)(k0 + r) * D3 + DMODEL + h * HDIM + c8;
            *(uint4*)&Ks[r * APH + c8] = *(const uint4*)kr;
            *(uint4*)&Vs[r * APH + c8] = *(const uint4*)(kr + DMODEL);
        }
        __syncthreads();

        if (k0 > q0 + wrow + 15) continue;         // warp fully masked

        float sacc[8][4];
#pragma unroll
        for (int nt = 0; nt < 8; nt++)
#pragma unroll
            for (int j = 0; j < 4; j++) sacc[nt][j] = 0.f;
#pragma unroll
        for (int kk = 0; kk < 4; kk++) {
            const int kb = kk * 16;
            uint32_t bf[8][2];
#pragma unroll
            for (int np = 0; np < 4; np++) {
                uint32_t bd = ksS + (uint32_t)((np * 16 + bRow) * APH + kb + bColSel) * 2u;
                LDSM_X4(bf[2 * np][0], bf[2 * np][1], bf[2 * np + 1][0], bf[2 * np + 1][1], bd);
            }
#pragma unroll
            for (int nt = 0; nt < 8; nt++)
                MMA_F16(sacc[nt], qf[kk], bf[nt]);
        }

        float tmax0 = -1e30f, tmax1 = -1e30f;
#pragma unroll
        for (int nt = 0; nt < 8; nt++) {
            int col = k0 + nt * 8 + 2 * tig;
            if (col     > r0g) sacc[nt][0] = -1e30f;
            if (col + 1 > r0g) sacc[nt][1] = -1e30f;
            if (col     > r1g) sacc[nt][2] = -1e30f;
            if (col + 1 > r1g) sacc[nt][3] = -1e30f;
            tmax0 = fmaxf(tmax0, fmaxf(sacc[nt][0], sacc[nt][1]));
            tmax1 = fmaxf(tmax1, fmaxf(sacc[nt][2], sacc[nt][3]));
        }
#pragma unroll
        for (int d = 1; d <= 2; d <<= 1) {
            tmax0 = fmaxf(tmax0, __shfl_xor_sync(0xffffffffu, tmax0, d));
            tmax1 = fmaxf(tmax1, __shfl_xor_sync(0xffffffffu, tmax1, d));
        }

        float mn0 = fmaxf(m0, tmax0), mn1 = fmaxf(m1, tmax1);
        float c0 = __expf(m0 - mn0), c1 = __expf(m1 - mn1);
        l0 *= c0; l1 *= c1; m0 = mn0; m1 = mn1;
#pragma unroll
        for (int nt = 0; nt < 8; nt++) {
            oacc[nt][0] *= c0; oacc[nt][1] *= c0;
            oacc[nt][2] *= c1; oacc[nt][3] *= c1;
        }

        __syncwarp();
#pragma unroll
        for (int nt = 0; nt < 8; nt++) {
            float p0 = __expf(sacc[nt][0] - m0);
            float p1 = __expf(sacc[nt][1] - m0);
            float p2 = __expf(sacc[nt][2] - m1);
            float p3 = __expf(sacc[nt][3] - m1);
            l0 += p0 + p1; l1 += p2 + p3;
            int col = nt * 8 + 2 * tig;
            *(__half2*)&Ps[(wrow + gid    ) * APH + col] = __floats2half2_rn(p0, p1);
            *(__half2*)&Ps[(wrow + gid + 8) * APH + col] = __floats2half2_rn(p2, p3);
        }
        __syncwarp();

#pragma unroll
        for (int kk = 0; kk < 4; kk++) {
            const int kb = kk * 16;
            uint32_t a[4];
            {
                uint32_t ad = psS + (uint32_t)((wrow + aRow) * APH + kb + aColSel) * 2u;
                LDSM_X4(a[0], a[1], a[2], a[3], ad);
            }
            uint32_t bv[8][2];
#pragma unroll
            for (int np = 0; np < 4; np++) {
                uint32_t vd = vsS + (uint32_t)((kb + vRow) * APH + np * 16 + vColSel) * 2u;
                LDSM_X4_T(bv[2 * np][0], bv[2 * np][1], bv[2 * np + 1][0], bv[2 * np + 1][1], vd);
            }
#pragma unroll
            for (int nt = 0; nt < 8; nt++)
                MMA_F16(oacc[nt], a, bv[nt]);
        }
    }

#pragma unroll
    for (int d = 1; d <= 2; d <<= 1) {
        l0 += __shfl_xor_sync(0xffffffffu, l0, d);
        l1 += __shfl_xor_sync(0xffffffffu, l1, d);
    }
    float inv0 = 1.f / l0, inv1 = 1.f / l1;
    __half* y0 = y + (size_t)(b * TSEQ + r0g) * DMODEL + h * HDIM;
    __half* y1 = y + (size_t)(b * TSEQ + r1g) * DMODEL + h * HDIM;
#pragma unroll
    for (int nt = 0; nt < 8; nt++) {
        int col = nt * 8 + 2 * tig;
        *(__half2*)(y0 + col) = __floats2half2_rn(oacc[nt][0] * inv0, oacc[nt][1] * inv0);
        *(__half2*)(y1 + col) = __floats2half2_rn(oacc[nt][2] * inv1, oacc[nt][3] * inv1);
    }
}

// ---------------------------------------------------------------------------
extern "C" void kernel_launch(void* const* d_in, const int* in_sizes, int n_in,
                              void* d_out, int out_size)
{
    (void)in_sizes; (void)n_in; (void)out_size;
    const float* x     = (const float*)d_in[0];
    const float* qkv_w = (const float*)d_in[1];
    const float* qkv_b = (const float*)d_in[2];
    const float* o_w   = (const float*)d_in[3];
    const float* o_b   = (const float*)d_in[4];
    float* out = (float*)d_out;

    __half *xh, *qkvh, *yh, *wqkvh, *woh;
    cudaGetSymbolAddress((void**)&xh, g_xh);
    cudaGetSymbolAddress((void**)&qkvh, g_qkvh);
    cudaGetSymbolAddress((void**)&yh, g_yh);
    cudaGetSymbolAddress((void**)&wqkvh, g_wqkvh);
    cudaGetSymbolAddress((void**)&woh, g_woh);

    cudaFuncSetAttribute(gemm_h_kernel<__half>,
                         cudaFuncAttributeMaxDynamicSharedMemorySize, HSMEM_BYTES);
    cudaFuncSetAttribute(gemm_h_kernel<float>,
                         cudaFuncAttributeMaxDynamicSharedMemorySize, HSMEM_BYTES);

    // prep: pure streaming fp32 -> fp16
    f2h_kernel<<<1024, 256>>>(x, xh, MROWS * DMODEL / 4);
    f2h_kernel<<<512, 256>>>(qkv_w, wqkvh, KDIM * D3 / 4);
    f2h_kernel<<<256, 256>>>(o_w, woh, KDIM * DMODEL / 4);

    // 1) QKV projection
    gemm_h_kernel<__half><<<dim3(D3 / 128, MROWS / 128), 256, HSMEM_BYTES>>>(
        xh, wqkvh, qkv_b, qkvh, D3);

    // 2) causal flash attention
    attn_h_kernel<<<dim3(TSEQ / 128, NBATCH * NHEADS), 256>>>(qkvh, yh);

    // 3) output projection
    gemm_h_kernel<float><<<dim3(DMODEL / 128, MROWS / 128), 256, HSMEM_BYTES>>>(
        yh, woh, o_b, out, DMODEL);
}

// round 10
// speedup vs baseline: 1.1239x; 1.0449x over previous
#include <cuda_runtime.h>
#include <cuda_fp16.h>
#include <cstdint>
#include <math.h>

#define NBATCH 4
#define TSEQ   2048
#define DMODEL 1024
#define NHEADS 16
#define HDIM   64
#define MROWS  (NBATCH * TSEQ)   // 8192
#define KDIM   DMODEL            // 1024
#define D3     (3 * DMODEL)

// ---------------- scratch (static device globals; no runtime alloc) --------
__device__ __align__(1024) __half g_xh[(size_t)MROWS * DMODEL];        // 16 MB
__device__ __align__(1024) __half g_qkvh[(size_t)MROWS * D3];          // 50 MB
__device__ __align__(1024) __half g_yh[(size_t)MROWS * DMODEL];        // 16 MB
__device__ __align__(1024) __half g_wqkvh[(size_t)KDIM * D3];          // 6 MB
__device__ __align__(1024) __half g_woh[(size_t)KDIM * DMODEL];        // 2 MB

// ---------------- helpers ---------------------------------------------------
#define CP_ASYNC16(dst, src) \
    asm volatile("cp.async.cg.shared.global [%0], [%1], 16;" \
                 :: "r"(dst), "l"(src) : "memory")
#define CP_COMMIT() asm volatile("cp.async.commit_group;" ::: "memory")
#define CP_WAIT1()  asm volatile("cp.async.wait_group 1;" ::: "memory")
#define CP_WAIT0()  asm volatile("cp.async.wait_group 0;" ::: "memory")

__device__ __forceinline__ uint32_t smem_u32(const void* p) {
    uint32_t a;
    asm("{ .reg .u64 t; cvta.to.shared.u64 t, %1; cvt.u32.u64 %0, t; }"
        : "=r"(a) : "l"(p));
    return a;
}

#define MMA_F16(d, a, b) \
    asm volatile("mma.sync.aligned.m16n8k16.row.col.f32.f16.f16.f32 " \
        "{%0,%1,%2,%3}, {%4,%5,%6,%7}, {%8,%9}, {%0,%1,%2,%3};" \
        : "+f"((d)[0]), "+f"((d)[1]), "+f"((d)[2]), "+f"((d)[3]) \
        : "r"((a)[0]), "r"((a)[1]), "r"((a)[2]), "r"((a)[3]), \
          "r"((b)[0]), "r"((b)[1]))

#define LDSM_X4(r0, r1, r2, r3, addr) \
    asm volatile("ldmatrix.sync.aligned.m8n8.x4.shared.b16 {%0,%1,%2,%3}, [%4];" \
        : "=r"(r0), "=r"(r1), "=r"(r2), "=r"(r3) : "r"(addr))
#define LDSM_X4_T(r0, r1, r2, r3, addr) \
    asm volatile("ldmatrix.sync.aligned.m8n8.x4.trans.shared.b16 {%0,%1,%2,%3}, [%4];" \
        : "=r"(r0), "=r"(r1), "=r"(r2), "=r"(r3) : "r"(addr))

__device__ __forceinline__ void store_pair(float* p, float a, float b) {
    *(float2*)p = make_float2(a, b);
}
__device__ __forceinline__ void store_pair(__half* p, float a, float b) {
    *(__half2*)p = __floats2half2_rn(a, b);
}

// ---------------- prep: fused fp32 -> fp16 convert (3 segments) ------------
__global__ void f2h3_kernel(const float* __restrict__ in0, __half* __restrict__ out0, int n0,
                            const float* __restrict__ in1, __half* __restrict__ out1, int n1,
                            const float* __restrict__ in2, __half* __restrict__ out2, int n2)
{
    const int ntot = n0 + n1 + n2;
    for (int i = blockIdx.x * blockDim.x + threadIdx.x; i < ntot;
         i += gridDim.x * blockDim.x) {
        const float* in; __half* out; int j = i;
        if (j < n0)            { in = in0; out = out0; }
        else if ((j -= n0) < n1) { in = in1; out = out1; }
        else                   { j -= n1; in = in2; out = out2; }
        float4 v = *(const float4*)(in + (size_t)j * 4);
        __half2 h0 = __floats2half2_rn(v.x, v.y);
        __half2 h1 = __floats2half2_rn(v.z, v.w);
        *(uint2*)(out + (size_t)j * 4) =
            make_uint2(*(uint32_t*)&h0, *(uint32_t*)&h1);
    }
}

// ---------------- fp16 mma GEMM (unchanged from R9) ------------------------
#define GBK 64
#define GAP 72
#define GBP 136
#define ATILE_H (128 * GAP)
#define BTILE_H (GBK * GBP)
#define STAGE_H (ATILE_H + BTILE_H)
#define HSMEM_BYTES (3 * STAGE_H * 2)        // 107520 B
#define GCHUNKS (KDIM / GBK)                 // 16

template <typename OutT>
__global__ __launch_bounds__(256, 2) void gemm_h_kernel(
    const __half* __restrict__ A, const __half* __restrict__ W,
    const float* __restrict__ bias, OutT* __restrict__ C, int N)
{
    extern __shared__ __half hsm[];
    const int tid = threadIdx.x;
    const int wid = tid >> 5;
    const int lane = tid & 31;
    const int gid = lane >> 2;
    const int tig = lane & 3;

    const size_t row0 = (size_t)blockIdx.y * 128;
    const size_t col0 = (size_t)blockIdx.x * 128;
    const int wm0 = (wid & 3) * 32;
    const int wn0 = (wid >> 2) * 64;

    const __half* Ab = A + row0 * KDIM;

    float acc[2][8][4];
#pragma unroll
    for (int mt = 0; mt < 2; mt++)
#pragma unroll
        for (int nt = 0; nt < 8; nt++)
#pragma unroll
            for (int j = 0; j < 4; j++) acc[mt][nt][j] = 0.f;

    const uint32_t sbase = smem_u32(hsm);

    const int aRow = lane & 15, aColSel = (lane >> 4) * 8;
    const int tRow = (lane & 7) + (((lane >> 3) & 1) << 3);
    const int tColSel = (lane >> 4) * 8;

    auto load_stage = [&](int s, int chunk) {
        const int kof = chunk * GBK;
        uint32_t aS = sbase + (uint32_t)(s * STAGE_H) * 2u;
        uint32_t bS = aS + (uint32_t)ATILE_H * 2u;
#pragma unroll
        for (int i = 0; i < 4; i++) {
            int idx = tid + i * 256;
            int r = idx >> 3, ch = idx & 7;
            CP_ASYNC16(aS + (uint32_t)(r * GAP + ch * 8) * 2u,
                       Ab + (size_t)r * KDIM + kof + ch * 8);
        }
#pragma unroll
        for (int i = 0; i < 4; i++) {
            int idx = tid + i * 256;
            int r = idx >> 4, ch = idx & 15;
            CP_ASYNC16(bS + (uint32_t)(r * GBP + ch * 8) * 2u,
                       W + (size_t)(kof + r) * N + col0 + ch * 8);
        }
    };

    load_stage(0, 0); CP_COMMIT();
    load_stage(1, 1); CP_COMMIT();

    for (int c = 0; c < GCHUNKS; c++) {
        CP_WAIT1();
        __syncthreads();
        if (c + 2 < GCHUNKS) load_stage((c + 2) % 3, c + 2);
        CP_COMMIT();

        const uint32_t aS = sbase + (uint32_t)((c % 3) * STAGE_H) * 2u;
        const uint32_t bS = aS + (uint32_t)ATILE_H * 2u;
#pragma unroll
        for (int kk = 0; kk < 4; kk++) {
            const int kb = kk * 16;
            uint32_t a[2][4];
#pragma unroll
            for (int mt = 0; mt < 2; mt++) {
                uint32_t ad = aS + (uint32_t)((wm0 + mt * 16 + aRow) * GAP + kb + aColSel) * 2u;
                LDSM_X4(a[mt][0], a[mt][1], a[mt][2], a[mt][3], ad);
            }
            uint32_t b[8][2];
#pragma unroll
            for (int np = 0; np < 4; np++) {
                uint32_t bd = bS + (uint32_t)((kb + tRow) * GBP + wn0 + np * 16 + tColSel) * 2u;
                LDSM_X4_T(b[2 * np][0], b[2 * np][1], b[2 * np + 1][0], b[2 * np + 1][1], bd);
            }
#pragma unroll
            for (int mt = 0; mt < 2; mt++)
#pragma unroll
                for (int nt = 0; nt < 8; nt++)
                    MMA_F16(acc[mt][nt], a[mt], b[nt]);
        }
    }

#pragma unroll
    for (int mt = 0; mt < 2; mt++) {
        size_t r = row0 + wm0 + mt * 16 + gid;
#pragma unroll
        for (int nt = 0; nt < 8; nt++) {
            size_t col = col0 + wn0 + nt * 8 + tig * 2;
            float2 bb = *(const float2*)(bias + col);
            store_pair(C + r * N + col, acc[mt][nt][0] + bb.x, acc[mt][nt][1] + bb.y);
            store_pair(C + (r + 8) * N + col, acc[mt][nt][2] + bb.x, acc[mt][nt][3] + bb.y);
        }
    }
}

// ---------------- fp16 flash attention: R9 compute + cp.async K/V ----------
// Per CTA one (b, h, 128-q tile); 8 warps x 16 q-rows; 64-key tiles.
// K/V double-buffered via cp.async (prefetch t+1 during compute t).
// Compute body identical to R9 (fully static unrolled loops).
#define APH 72
#define KVT_H (64 * APH)                          // 4608 halves per K or V tile
#define ATT_SMEM_BYTES ((4 * KVT_H + 128 * APH) * 2)   // 55296 B

__global__ __launch_bounds__(256, 2) void attn_h_kernel(
    const __half* __restrict__ qkv, __half* __restrict__ y)
{
    extern __shared__ __half dsm[];
    __half* Ps = dsm + 4 * KVT_H;

    const int qb  = gridDim.x - 1 - blockIdx.x;
    const int bh  = blockIdx.y;
    const int b   = bh >> 4;
    const int h   = bh & 15;
    const int tid = threadIdx.x;
    const int wid = tid >> 5;
    const int lane = tid & 31;
    const int gid = lane >> 2;
    const int tig = lane & 3;
    const int wrow = wid * 16;
    const int q0 = qb * 128;

    const __half* base = qkv + (size_t)b * TSEQ * D3;
    const uint32_t smS = smem_u32(dsm);
    const uint32_t psS = smem_u32(Ps);

    const int aRow = lane & 15, aColSel = (lane >> 4) * 8;
    const int bRow = (lane & 7) + ((lane >> 4) << 3);
    const int bColSel = ((lane >> 3) & 1) * 8;
    const int vRow = (lane & 7) + (((lane >> 3) & 1) << 3);
    const int vColSel = (lane >> 4) * 8;

    const int ntiles = (qb + 1) * 2;

    auto load_kv = [&](int t, int s) {
        const int k0 = t * 64;
        uint32_t kS = smS + (uint32_t)(s * 2 * KVT_H) * 2u;
        uint32_t vS = kS + (uint32_t)KVT_H * 2u;
        const __half* kb_ = base + (size_t)k0 * D3 + DMODEL + h * HDIM;
#pragma unroll
        for (int i = 0; i < 2; i++) {
            int idx = tid + i * 256;
            int r = idx >> 3, ch = idx & 7;
            uint32_t off = (uint32_t)(r * APH + ch * 8) * 2u;
            const __half* src = kb_ + (size_t)r * D3 + ch * 8;
            CP_ASYNC16(kS + off, src);
            CP_ASYNC16(vS + off, src + DMODEL);
        }
    };

    // prologue: kick tile-0 K/V load, stage Q while it flies
    load_kv(0, 0); CP_COMMIT();

    {
        const __half2 s = __float2half2_rn(0.125f);
#pragma unroll
        for (int i = 0; i < 4; i++) {
            int idx = tid + i * 256;
            int r = idx >> 3, c8 = (idx & 7) << 3;
            uint4 v = *(const uint4*)(base + (size_t)(q0 + r) * D3 + h * HDIM + c8);
            __half2* h2 = reinterpret_cast<__half2*>(&v);
            h2[0] = __hmul2(h2[0], s); h2[1] = __hmul2(h2[1], s);
            h2[2] = __hmul2(h2[2], s); h2[3] = __hmul2(h2[3], s);
            *(uint4*)&Ps[r * APH + c8] = v;
        }
    }
    __syncthreads();

    uint32_t qf[4][4];
#pragma unroll
    for (int kk = 0; kk < 4; kk++) {
        uint32_t ad = psS + (uint32_t)((wrow + aRow) * APH + kk * 16 + aColSel) * 2u;
        LDSM_X4(qf[kk][0], qf[kk][1], qf[kk][2], qf[kk][3], ad);
    }

    const int r0g = q0 + wrow + gid;
    const int r1g = r0g + 8;

    float m0 = -1e30f, m1 = -1e30f, l0 = 0.f, l1 = 0.f;
    float oacc[8][4];
#pragma unroll
    for (int nt = 0; nt < 8; nt++)
#pragma unroll
        for (int j = 0; j < 4; j++) oacc[nt][j] = 0.f;

    for (int t = 0; t < ntiles; t++) {
        const int k0 = t * 64;
        CP_WAIT0();
        __syncthreads();            // tile t visible; prev compute done (buffer reuse safe)
        if (t + 1 < ntiles) { load_kv(t + 1, (t + 1) & 1); CP_COMMIT(); }

        if (k0 > q0 + wrow + 15) continue;   // warp fully masked

        const uint32_t kS = smS + (uint32_t)((t & 1) * 2 * KVT_H) * 2u;
        const uint32_t vS = kS + (uint32_t)KVT_H * 2u;

        // ---- S = Q @ K^T ----
        float sacc[8][4];
#pragma unroll
        for (int nt = 0; nt < 8; nt++)
#pragma unroll
            for (int j = 0; j < 4; j++) sacc[nt][j] = 0.f;
#pragma unroll
        for (int kk = 0; kk < 4; kk++) {
            const int kb = kk * 16;
            uint32_t bf[8][2];
#pragma unroll
            for (int np = 0; np < 4; np++) {
                uint32_t bd = kS + (uint32_t)((np * 16 + bRow) * APH + kb + bColSel) * 2u;
                LDSM_X4(bf[2 * np][0], bf[2 * np][1], bf[2 * np + 1][0], bf[2 * np + 1][1], bd);
            }
#pragma unroll
            for (int nt = 0; nt < 8; nt++)
                MMA_F16(sacc[nt], qf[kk], bf[nt]);
        }

        // ---- causal mask + quad row max ----
        float tmax0 = -1e30f, tmax1 = -1e30f;
#pragma unroll
        for (int nt = 0; nt < 8; nt++) {
            int col = k0 + nt * 8 + 2 * tig;
            if (col     > r0g) sacc[nt][0] = -1e30f;
            if (col + 1 > r0g) sacc[nt][1] = -1e30f;
            if (col     > r1g) sacc[nt][2] = -1e30f;
            if (col + 1 > r1g) sacc[nt][3] = -1e30f;
            tmax0 = fmaxf(tmax0, fmaxf(sacc[nt][0], sacc[nt][1]));
            tmax1 = fmaxf(tmax1, fmaxf(sacc[nt][2], sacc[nt][3]));
        }
#pragma unroll
        for (int d = 1; d <= 2; d <<= 1) {
            tmax0 = fmaxf(tmax0, __shfl_xor_sync(0xffffffffu, tmax0, d));
            tmax1 = fmaxf(tmax1, __shfl_xor_sync(0xffffffffu, tmax1, d));
        }

        float mn0 = fmaxf(m0, tmax0), mn1 = fmaxf(m1, tmax1);
        float c0 = __expf(m0 - mn0), c1 = __expf(m1 - mn1);
        l0 *= c0; l1 *= c1; m0 = mn0; m1 = mn1;
#pragma unroll
        for (int nt = 0; nt < 8; nt++) {
            oacc[nt][0] *= c0; oacc[nt][1] *= c0;
            oacc[nt][2] *= c1; oacc[nt][3] *= c1;
        }

        // ---- P = exp(S - m); partial l; store P (warp-private rows) ----
        __syncwarp();
#pragma unroll
        for (int nt = 0; nt < 8; nt++) {
            float p0 = __expf(sacc[nt][0] - m0);
            float p1 = __expf(sacc[nt][1] - m0);
            float p2 = __expf(sacc[nt][2] - m1);
            float p3 = __expf(sacc[nt][3] - m1);
            l0 += p0 + p1; l1 += p2 + p3;
            int col = nt * 8 + 2 * tig;
            *(__half2*)&Ps[(wrow + gid    ) * APH + col] = __floats2half2_rn(p0, p1);
            *(__half2*)&Ps[(wrow + gid + 8) * APH + col] = __floats2half2_rn(p2, p3);
        }
        __syncwarp();

        // ---- O += P @ V ----
#pragma unroll
        for (int kk = 0; kk < 4; kk++) {
            const int kb = kk * 16;
            uint32_t a[4];
            {
                uint32_t ad = psS + (uint32_t)((wrow + aRow) * APH + kb + aColSel) * 2u;
                LDSM_X4(a[0], a[1], a[2], a[3], ad);
            }
            uint32_t bv[8][2];
#pragma unroll
            for (int np = 0; np < 4; np++) {
                uint32_t vd = vS + (uint32_t)((kb + vRow) * APH + np * 16 + vColSel) * 2u;
                LDSM_X4_T(bv[2 * np][0], bv[2 * np][1], bv[2 * np + 1][0], bv[2 * np + 1][1], vd);
            }
#pragma unroll
            for (int nt = 0; nt < 8; nt++)
                MMA_F16(oacc[nt], a, bv[nt]);
        }
    }

    // ---- quad-reduce partial row sums, normalize, store half y ----
#pragma unroll
    for (int d = 1; d <= 2; d <<= 1) {
        l0 += __shfl_xor_sync(0xffffffffu, l0, d);
        l1 += __shfl_xor_sync(0xffffffffu, l1, d);
    }
    float inv0 = 1.f / l0, inv1 = 1.f / l1;
    __half* y0 = y + (size_t)(b * TSEQ + r0g) * DMODEL + h * HDIM;
    __half* y1 = y + (size_t)(b * TSEQ + r1g) * DMODEL + h * HDIM;
#pragma unroll
    for (int nt = 0; nt < 8; nt++) {
        int col = nt * 8 + 2 * tig;
        *(__half2*)(y0 + col) = __floats2half2_rn(oacc[nt][0] * inv0, oacc[nt][1] * inv0);
        *(__half2*)(y1 + col) = __floats2half2_rn(oacc[nt][2] * inv1, oacc[nt][3] * inv1);
    }
}

// ---------------------------------------------------------------------------
extern "C" void kernel_launch(void* const* d_in, const int* in_sizes, int n_in,
                              void* d_out, int out_size)
{
    (void)in_sizes; (void)n_in; (void)out_size;
    const float* x     = (const float*)d_in[0];
    const float* qkv_w = (const float*)d_in[1];
    const float* qkv_b = (const float*)d_in[2];
    const float* o_w   = (const float*)d_in[3];
    const float* o_b   = (const float*)d_in[4];
    float* out = (float*)d_out;

    __half *xh, *qkvh, *yh, *wqkvh, *woh;
    cudaGetSymbolAddress((void**)&xh, g_xh);
    cudaGetSymbolAddress((void**)&qkvh, g_qkvh);
    cudaGetSymbolAddress((void**)&yh, g_yh);
    cudaGetSymbolAddress((void**)&wqkvh, g_wqkvh);
    cudaGetSymbolAddress((void**)&woh, g_woh);

    cudaFuncSetAttribute(gemm_h_kernel<__half>,
                         cudaFuncAttributeMaxDynamicSharedMemorySize, HSMEM_BYTES);
    cudaFuncSetAttribute(gemm_h_kernel<float>,
                         cudaFuncAttributeMaxDynamicSharedMemorySize, HSMEM_BYTES);
    cudaFuncSetAttribute(attn_h_kernel,
                         cudaFuncAttributeMaxDynamicSharedMemorySize, ATT_SMEM_BYTES);

    // prep: single fused fp32 -> fp16 conversion (x, qkv_w, o_w)
    f2h3_kernel<<<1480, 256>>>(x, xh, MROWS * DMODEL / 4,
                               qkv_w, wqkvh, KDIM * D3 / 4,
                               o_w, woh, KDIM * DMODEL / 4);

    // 1) QKV projection
    gemm_h_kernel<__half><<<dim3(D3 / 128, MROWS / 128), 256, HSMEM_BYTES>>>(
        xh, wqkvh, qkv_b, qkvh, D3);

    // 2) causal flash attention
    attn_h_kernel<<<dim3(TSEQ / 128, NBATCH * NHEADS), 256, ATT_SMEM_BYTES>>>(
        qkvh, yh);

    // 3) output projection
    gemm_h_kernel<float><<<dim3(DMODEL / 128, MROWS / 128), 256, HSMEM_BYTES>>>(
        yh, woh, o_b, out, DMODEL);
}

// round 11
// speedup vs baseline: 1.1455x; 1.0192x over previous
#include <cuda_runtime.h>
#include <cuda_fp16.h>
#include <cstdint>
#include <math.h>

#define NBATCH 4
#define TSEQ   2048
#define DMODEL 1024
#define NHEADS 16
#define HDIM   64
#define MROWS  (NBATCH * TSEQ)   // 8192
#define KDIM   DMODEL            // 1024
#define D3     (3 * DMODEL)

// ---------------- scratch (static device globals; no runtime alloc) --------
__device__ __align__(1024) __half g_xh[(size_t)MROWS * DMODEL];        // 16 MB
__device__ __align__(1024) __half g_qkvh[(size_t)MROWS * D3];          // 50 MB
__device__ __align__(1024) __half g_yh[(size_t)MROWS * DMODEL];        // 16 MB
__device__ __align__(1024) __half g_wqkvh[(size_t)KDIM * D3];          // 6 MB
__device__ __align__(1024) __half g_woh[(size_t)KDIM * DMODEL];        // 2 MB

// ---------------- helpers ---------------------------------------------------
#define CP_ASYNC16(dst, src) \
    asm volatile("cp.async.cg.shared.global [%0], [%1], 16;" \
                 :: "r"(dst), "l"(src) : "memory")
#define CP_COMMIT() asm volatile("cp.async.commit_group;" ::: "memory")
#define CP_WAIT1()  asm volatile("cp.async.wait_group 1;" ::: "memory")
#define CP_WAIT0()  asm volatile("cp.async.wait_group 0;" ::: "memory")

__device__ __forceinline__ uint32_t smem_u32(const void* p) {
    uint32_t a;
    asm("{ .reg .u64 t; cvta.to.shared.u64 t, %1; cvt.u32.u64 %0, t; }"
        : "=r"(a) : "l"(p));
    return a;
}

#define MMA_F16(d, a, b) \
    asm volatile("mma.sync.aligned.m16n8k16.row.col.f32.f16.f16.f32 " \
        "{%0,%1,%2,%3}, {%4,%5,%6,%7}, {%8,%9}, {%0,%1,%2,%3};" \
        : "+f"((d)[0]), "+f"((d)[1]), "+f"((d)[2]), "+f"((d)[3]) \
        : "r"((a)[0]), "r"((a)[1]), "r"((a)[2]), "r"((a)[3]), \
          "r"((b)[0]), "r"((b)[1]))

#define LDSM_X4(r0, r1, r2, r3, addr) \
    asm volatile("ldmatrix.sync.aligned.m8n8.x4.shared.b16 {%0,%1,%2,%3}, [%4];" \
        : "=r"(r0), "=r"(r1), "=r"(r2), "=r"(r3) : "r"(addr))
#define LDSM_X4_T(r0, r1, r2, r3, addr) \
    asm volatile("ldmatrix.sync.aligned.m8n8.x4.trans.shared.b16 {%0,%1,%2,%3}, [%4];" \
        : "=r"(r0), "=r"(r1), "=r"(r2), "=r"(r3) : "r"(addr))

__device__ __forceinline__ void store_pair(float* p, float a, float b) {
    *(float2*)p = make_float2(a, b);
}
__device__ __forceinline__ void store_pair(__half* p, float a, float b) {
    *(__half2*)p = __floats2half2_rn(a, b);
}

// sum the two half lanes of a half2 into fp32 (HADD w/ lane sel + F2F)
__device__ __forceinline__ float h2sum(__half2 v) {
    return __half2float(__hadd(__low2half(v), __high2half(v)));
}

// ---------------- prep: fused fp32 -> fp16 convert (3 segments) ------------
__global__ void f2h3_kernel(const float* __restrict__ in0, __half* __restrict__ out0, int n0,
                            const float* __restrict__ in1, __half* __restrict__ out1, int n1,
                            const float* __restrict__ in2, __half* __restrict__ out2, int n2)
{
    const int ntot = n0 + n1 + n2;
    for (int i = blockIdx.x * blockDim.x + threadIdx.x; i < ntot;
         i += gridDim.x * blockDim.x) {
        const float* in; __half* out; int j = i;
        if (j < n0)            { in = in0; out = out0; }
        else if ((j -= n0) < n1) { in = in1; out = out1; }
        else                   { j -= n1; in = in2; out = out2; }
        float4 v = *(const float4*)(in + (size_t)j * 4);
        __half2 h0 = __floats2half2_rn(v.x, v.y);
        __half2 h1 = __floats2half2_rn(v.z, v.w);
        *(uint2*)(out + (size_t)j * 4) =
            make_uint2(*(uint32_t*)&h0, *(uint32_t*)&h1);
    }
}

// ---------------- fp16 mma GEMM (unchanged from R9/R10) --------------------
#define GBK 64
#define GAP 72
#define GBP 136
#define ATILE_H (128 * GAP)
#define BTILE_H (GBK * GBP)
#define STAGE_H (ATILE_H + BTILE_H)
#define HSMEM_BYTES (3 * STAGE_H * 2)        // 107520 B
#define GCHUNKS (KDIM / GBK)                 // 16

template <typename OutT>
__global__ __launch_bounds__(256, 2) void gemm_h_kernel(
    const __half* __restrict__ A, const __half* __restrict__ W,
    const float* __restrict__ bias, OutT* __restrict__ C, int N)
{
    extern __shared__ __half hsm[];
    const int tid = threadIdx.x;
    const int wid = tid >> 5;
    const int lane = tid & 31;
    const int gid = lane >> 2;
    const int tig = lane & 3;

    const size_t row0 = (size_t)blockIdx.y * 128;
    const size_t col0 = (size_t)blockIdx.x * 128;
    const int wm0 = (wid & 3) * 32;
    const int wn0 = (wid >> 2) * 64;

    const __half* Ab = A + row0 * KDIM;

    float acc[2][8][4];
#pragma unroll
    for (int mt = 0; mt < 2; mt++)
#pragma unroll
        for (int nt = 0; nt < 8; nt++)
#pragma unroll
            for (int j = 0; j < 4; j++) acc[mt][nt][j] = 0.f;

    const uint32_t sbase = smem_u32(hsm);

    const int aRow = lane & 15, aColSel = (lane >> 4) * 8;
    const int tRow = (lane & 7) + (((lane >> 3) & 1) << 3);
    const int tColSel = (lane >> 4) * 8;

    auto load_stage = [&](int s, int chunk) {
        const int kof = chunk * GBK;
        uint32_t aS = sbase + (uint32_t)(s * STAGE_H) * 2u;
        uint32_t bS = aS + (uint32_t)ATILE_H * 2u;
#pragma unroll
        for (int i = 0; i < 4; i++) {
            int idx = tid + i * 256;
            int r = idx >> 3, ch = idx & 7;
            CP_ASYNC16(aS + (uint32_t)(r * GAP + ch * 8) * 2u,
                       Ab + (size_t)r * KDIM + kof + ch * 8);
        }
#pragma unroll
        for (int i = 0; i < 4; i++) {
            int idx = tid + i * 256;
            int r = idx >> 4, ch = idx & 15;
            CP_ASYNC16(bS + (uint32_t)(r * GBP + ch * 8) * 2u,
                       W + (size_t)(kof + r) * N + col0 + ch * 8);
        }
    };

    load_stage(0, 0); CP_COMMIT();
    load_stage(1, 1); CP_COMMIT();

    for (int c = 0; c < GCHUNKS; c++) {
        CP_WAIT1();
        __syncthreads();
        if (c + 2 < GCHUNKS) load_stage((c + 2) % 3, c + 2);
        CP_COMMIT();

        const uint32_t aS = sbase + (uint32_t)((c % 3) * STAGE_H) * 2u;
        const uint32_t bS = aS + (uint32_t)ATILE_H * 2u;
#pragma unroll
        for (int kk = 0; kk < 4; kk++) {
            const int kb = kk * 16;
            uint32_t a[2][4];
#pragma unroll
            for (int mt = 0; mt < 2; mt++) {
                uint32_t ad = aS + (uint32_t)((wm0 + mt * 16 + aRow) * GAP + kb + aColSel) * 2u;
                LDSM_X4(a[mt][0], a[mt][1], a[mt][2], a[mt][3], ad);
            }
            uint32_t b[8][2];
#pragma unroll
            for (int np = 0; np < 4; np++) {
                uint32_t bd = bS + (uint32_t)((kb + tRow) * GBP + wn0 + np * 16 + tColSel) * 2u;
                LDSM_X4_T(b[2 * np][0], b[2 * np][1], b[2 * np + 1][0], b[2 * np + 1][1], bd);
            }
#pragma unroll
            for (int mt = 0; mt < 2; mt++)
#pragma unroll
                for (int nt = 0; nt < 8; nt++)
                    MMA_F16(acc[mt][nt], a[mt], b[nt]);
        }
    }

#pragma unroll
    for (int mt = 0; mt < 2; mt++) {
        size_t r = row0 + wm0 + mt * 16 + gid;
#pragma unroll
        for (int nt = 0; nt < 8; nt++) {
            size_t col = col0 + wn0 + nt * 8 + tig * 2;
            float2 bb = *(const float2*)(bias + col);
            store_pair(C + r * N + col, acc[mt][nt][0] + bb.x, acc[mt][nt][1] + bb.y);
            store_pair(C + (r + 8) * N + col, acc[mt][nt][2] + bb.x, acc[mt][nt][3] + bb.y);
        }
    }
}

// ---------------- fp16 flash attention: log2-domain softmax ----------------
// Q pre-scaled by 0.125*log2(e) => S in log2 domain; P = ex2.approx.f16x2
// (half the MUFU ops of fp32 __expf). l accumulated in fp32 from the SAME
// half P values (num/den consistent), rescales via exp2f.
#define APH 72
#define KVT_H (64 * APH)
#define ATT_SMEM_BYTES ((4 * KVT_H + 128 * APH) * 2)   // 55296 B

__global__ __launch_bounds__(256, 2) void attn_h_kernel(
    const __half* __restrict__ qkv, __half* __restrict__ y)
{
    extern __shared__ __half dsm[];
    __half* Ps = dsm + 4 * KVT_H;

    const int qb  = gridDim.x - 1 - blockIdx.x;
    const int bh  = blockIdx.y;
    const int b   = bh >> 4;
    const int h   = bh & 15;
    const int tid = threadIdx.x;
    const int wid = tid >> 5;
    const int lane = tid & 31;
    const int gid = lane >> 2;
    const int tig = lane & 3;
    const int wrow = wid * 16;
    const int q0 = qb * 128;

    const __half* base = qkv + (size_t)b * TSEQ * D3;
    const uint32_t smS = smem_u32(dsm);
    const uint32_t psS = smem_u32(Ps);

    const int aRow = lane & 15, aColSel = (lane >> 4) * 8;
    const int bRow = (lane & 7) + ((lane >> 4) << 3);
    const int bColSel = ((lane >> 3) & 1) * 8;
    const int vRow = (lane & 7) + (((lane >> 3) & 1) << 3);
    const int vColSel = (lane >> 4) * 8;

    const int ntiles = (qb + 1) * 2;

    auto load_kv = [&](int t, int s) {
        const int k0 = t * 64;
        uint32_t kS = smS + (uint32_t)(s * 2 * KVT_H) * 2u;
        uint32_t vS = kS + (uint32_t)KVT_H * 2u;
        const __half* kb_ = base + (size_t)k0 * D3 + DMODEL + h * HDIM;
#pragma unroll
        for (int i = 0; i < 2; i++) {
            int idx = tid + i * 256;
            int r = idx >> 3, ch = idx & 7;
            uint32_t off = (uint32_t)(r * APH + ch * 8) * 2u;
            const __half* src = kb_ + (size_t)r * D3 + ch * 8;
            CP_ASYNC16(kS + off, src);
            CP_ASYNC16(vS + off, src + DMODEL);
        }
    };

    // prologue: kick tile-0 K/V load, stage Q while it flies
    load_kv(0, 0); CP_COMMIT();

    {
        // 0.125 / sqrt-scale folded with log2(e): S ends up in log2 domain
        const __half2 s = __float2half2_rn(0.125f * 1.44269504089f);
#pragma unroll
        for (int i = 0; i < 4; i++) {
            int idx = tid + i * 256;
            int r = idx >> 3, c8 = (idx & 7) << 3;
            uint4 v = *(const uint4*)(base + (size_t)(q0 + r) * D3 + h * HDIM + c8);
            __half2* h2 = reinterpret_cast<__half2*>(&v);
            h2[0] = __hmul2(h2[0], s); h2[1] = __hmul2(h2[1], s);
            h2[2] = __hmul2(h2[2], s); h2[3] = __hmul2(h2[3], s);
            *(uint4*)&Ps[r * APH + c8] = v;
        }
    }
    __syncthreads();

    uint32_t qf[4][4];
#pragma unroll
    for (int kk = 0; kk < 4; kk++) {
        uint32_t ad = psS + (uint32_t)((wrow + aRow) * APH + kk * 16 + aColSel) * 2u;
        LDSM_X4(qf[kk][0], qf[kk][1], qf[kk][2], qf[kk][3], ad);
    }

    const int r0g = q0 + wrow + gid;
    const int r1g = r0g + 8;

    float m0 = -1e30f, m1 = -1e30f, l0 = 0.f, l1 = 0.f;
    float oacc[8][4];
#pragma unroll
    for (int nt = 0; nt < 8; nt++)
#pragma unroll
        for (int j = 0; j < 4; j++) oacc[nt][j] = 0.f;

    for (int t = 0; t < ntiles; t++) {
        const int k0 = t * 64;
        CP_WAIT0();
        __syncthreads();
        if (t + 1 < ntiles) { load_kv(t + 1, (t + 1) & 1); CP_COMMIT(); }

        if (k0 > q0 + wrow + 15) continue;   // warp fully masked

        const uint32_t kS = smS + (uint32_t)((t & 1) * 2 * KVT_H) * 2u;
        const uint32_t vS = kS + (uint32_t)KVT_H * 2u;

        // ---- S = Q @ K^T (log2 domain) ----
        float sacc[8][4];
#pragma unroll
        for (int nt = 0; nt < 8; nt++)
#pragma unroll
            for (int j = 0; j < 4; j++) sacc[nt][j] = 0.f;
#pragma unroll
        for (int kk = 0; kk < 4; kk++) {
            const int kb = kk * 16;
            uint32_t bf[8][2];
#pragma unroll
            for (int np = 0; np < 4; np++) {
                uint32_t bd = kS + (uint32_t)((np * 16 + bRow) * APH + kb + bColSel) * 2u;
                LDSM_X4(bf[2 * np][0], bf[2 * np][1], bf[2 * np + 1][0], bf[2 * np + 1][1], bd);
            }
#pragma unroll
            for (int nt = 0; nt < 8; nt++)
                MMA_F16(sacc[nt], qf[kk], bf[nt]);
        }

        // ---- causal mask + quad row max ----
        float tmax0 = -1e30f, tmax1 = -1e30f;
#pragma unroll
        for (int nt = 0; nt < 8; nt++) {
            int col = k0 + nt * 8 + 2 * tig;
            if (col     > r0g) sacc[nt][0] = -1e30f;
            if (col + 1 > r0g) sacc[nt][1] = -1e30f;
            if (col     > r1g) sacc[nt][2] = -1e30f;
            if (col + 1 > r1g) sacc[nt][3] = -1e30f;
            tmax0 = fmaxf(tmax0, fmaxf(sacc[nt][0], sacc[nt][1]));
            tmax1 = fmaxf(tmax1, fmaxf(sacc[nt][2], sacc[nt][3]));
        }
#pragma unroll
        for (int d = 1; d <= 2; d <<= 1) {
            tmax0 = fmaxf(tmax0, __shfl_xor_sync(0xffffffffu, tmax0, d));
            tmax1 = fmaxf(tmax1, __shfl_xor_sync(0xffffffffu, tmax1, d));
        }

        float mn0 = fmaxf(m0, tmax0), mn1 = fmaxf(m1, tmax1);
        float c0 = exp2f(m0 - mn0), c1 = exp2f(m1 - mn1);
        l0 *= c0; l1 *= c1; m0 = mn0; m1 = mn1;
#pragma unroll
        for (int nt = 0; nt < 8; nt++) {
            oacc[nt][0] *= c0; oacc[nt][1] *= c0;
            oacc[nt][2] *= c1; oacc[nt][3] *= c1;
        }

        // ---- P = 2^(S - m) via ex2.approx.f16x2; l from same half values ----
        __syncwarp();
#pragma unroll
        for (int nt = 0; nt < 8; nt++) {
            __half2 h01 = __floats2half2_rn(sacc[nt][0] - m0, sacc[nt][1] - m0);
            __half2 h23 = __floats2half2_rn(sacc[nt][2] - m1, sacc[nt][3] - m1);
            __half2 p01 = h2exp2(h01);
            __half2 p23 = h2exp2(h23);
            int col = nt * 8 + 2 * tig;
            *(__half2*)&Ps[(wrow + gid    ) * APH + col] = p01;
            *(__half2*)&Ps[(wrow + gid + 8) * APH + col] = p23;
            l0 += h2sum(p01);
            l1 += h2sum(p23);
        }
        __syncwarp();

        // ---- O += P @ V ----
#pragma unroll
        for (int kk = 0; kk < 4; kk++) {
            const int kb = kk * 16;
            uint32_t a[4];
            {
                uint32_t ad = psS + (uint32_t)((wrow + aRow) * APH + kb + aColSel) * 2u;
                LDSM_X4(a[0], a[1], a[2], a[3], ad);
            }
            uint32_t bv[8][2];
#pragma unroll
            for (int np = 0; np < 4; np++) {
                uint32_t vd = vS + (uint32_t)((kb + vRow) * APH + np * 16 + vColSel) * 2u;
                LDSM_X4_T(bv[2 * np][0], bv[2 * np][1], bv[2 * np + 1][0], bv[2 * np + 1][1], vd);
            }
#pragma unroll
            for (int nt = 0; nt < 8; nt++)
                MMA_F16(oacc[nt], a, bv[nt]);
        }
    }

    // ---- quad-reduce partial row sums, normalize, store half y ----
#pragma unroll
    for (int d = 1; d <= 2; d <<= 1) {
        l0 += __shfl_xor_sync(0xffffffffu, l0, d);
        l1 += __shfl_xor_sync(0xffffffffu, l1, d);
    }
    float inv0 = 1.f / l0, inv1 = 1.f / l1;
    __half* y0 = y + (size_t)(b * TSEQ + r0g) * DMODEL + h * HDIM;
    __half* y1 = y + (size_t)(b * TSEQ + r1g) * DMODEL + h * HDIM;
#pragma unroll
    for (int nt = 0; nt < 8; nt++) {
        int col = nt * 8 + 2 * tig;
        *(__half2*)(y0 + col) = __floats2half2_rn(oacc[nt][0] * inv0, oacc[nt][1] * inv0);
        *(__half2*)(y1 + col) = __floats2half2_rn(oacc[nt][2] * inv1, oacc[nt][3] * inv1);
    }
}

// ---------------------------------------------------------------------------
extern "C" void kernel_launch(void* const* d_in, const int* in_sizes, int n_in,
                              void* d_out, int out_size)
{
    (void)in_sizes; (void)n_in; (void)out_size;
    const float* x     = (const float*)d_in[0];
    const float* qkv_w = (const float*)d_in[1];
    const float* qkv_b = (const float*)d_in[2];
    const float* o_w   = (const float*)d_in[3];
    const float* o_b   = (const float*)d_in[4];
    float* out = (float*)d_out;

    __half *xh, *qkvh, *yh, *wqkvh, *woh;
    cudaGetSymbolAddress((void**)&xh, g_xh);
    cudaGetSymbolAddress((void**)&qkvh, g_qkvh);
    cudaGetSymbolAddress((void**)&yh, g_yh);
    cudaGetSymbolAddress((void**)&wqkvh, g_wqkvh);
    cudaGetSymbolAddress((void**)&woh, g_woh);

    cudaFuncSetAttribute(gemm_h_kernel<__half>,
                         cudaFuncAttributeMaxDynamicSharedMemorySize, HSMEM_BYTES);
    cudaFuncSetAttribute(gemm_h_kernel<float>,
                         cudaFuncAttributeMaxDynamicSharedMemorySize, HSMEM_BYTES);
    cudaFuncSetAttribute(attn_h_kernel,
                         cudaFuncAttributeMaxDynamicSharedMemorySize, ATT_SMEM_BYTES);

    // prep: single fused fp32 -> fp16 conversion (x, qkv_w, o_w)
    f2h3_kernel<<<1480, 256>>>(x, xh, MROWS * DMODEL / 4,
                               qkv_w, wqkvh, KDIM * D3 / 4,
                               o_w, woh, KDIM * DMODEL / 4);

    // 1) QKV projection
    gemm_h_kernel<__half><<<dim3(D3 / 128, MROWS / 128), 256, HSMEM_BYTES>>>(
        xh, wqkvh, qkv_b, qkvh, D3);

    // 2) causal flash attention
    attn_h_kernel<<<dim3(TSEQ / 128, NBATCH * NHEADS), 256, ATT_SMEM_BYTES>>>(
        qkvh, yh);

    // 3) output projection
    gemm_h_kernel<float><<<dim3(DMODEL / 128, MROWS / 128), 256, HSMEM_BYTES>>>(
        yh, woh, o_b, out, DMODEL);
}